// round 9
// baseline (speedup 1.0000x reference)
#include <cuda_runtime.h>
#include <cstddef>
#include <cstdint>

// Butterfly n=1024, log_n=10, increasing stride, + bias. 32768 rows.
//
// R8 = R4 compute core (512 thr, one pair/thread, pre-permuted zero-select
// twiddles; exchanges: stages 0-4 shfl_xor, 5-8 smem w/ minimal-scope named
// barriers; 2 rows/iter) + 1D TMA BULK input pipeline:
// cp.async.bulk.shared::cta.global loads 8KB (2 contiguous rows) per
// block-iter into a 3-slot ring, mbarrier complete_tx per slot, pipeline
// distance 2 (32KB/SM in flight). Input bytes bypass L1tex/LSU entirely
// (bulk engine / tma pipe). Ring reuse is ordered by the existing full-block
// barrier. Outputs remain __stcs.

constexpr int TPB  = 512;
constexpr int GRID = 296;

__device__ __forceinline__ void barx(int id, int cnt) {
    asm volatile("bar.sync %0, %1;" :: "r"(id), "r"(cnt) : "memory");
}
__device__ __forceinline__ void mbar_init(uint32_t a, uint32_t cnt) {
    asm volatile("mbarrier.init.shared.b64 [%0], %1;" :: "r"(a), "r"(cnt) : "memory");
}
__device__ __forceinline__ void mbar_expect_tx(uint32_t a, uint32_t bytes) {
    asm volatile("mbarrier.arrive.expect_tx.shared.b64 _, [%0], %1;" :: "r"(a), "r"(bytes) : "memory");
}
__device__ __forceinline__ void bulk_ld(uint32_t dst, const void* src, uint32_t bytes, uint32_t mbar) {
    asm volatile("cp.async.bulk.shared::cta.global.mbarrier::complete_tx::bytes [%0], [%1], %2, [%3];"
                 :: "r"(dst), "l"(src), "r"(bytes), "r"(mbar) : "memory");
}
__device__ __forceinline__ void mbar_wait(uint32_t a, uint32_t parity) {
    asm volatile(
        "{\n\t"
        ".reg .pred P;\n\t"
        "LW%=:\n\t"
        "mbarrier.try_wait.parity.acquire.cta.shared::cta.b64 P, [%0], %1, 0x989680;\n\t"
        "@P bra.uni LD%=;\n\t"
        "bra.uni LW%=;\n\t"
        "LD%=:\n\t"
        "}"
        :: "r"(a), "r"(parity) : "memory");
}

__global__ __launch_bounds__(TPB, 2)
void butterfly_kernel(const float* __restrict__ x,
                      const float* __restrict__ tw,
                      const float* __restrict__ bias,
                      float* __restrict__ out,
                      int nrows)
{
    __shared__ __align__(16) float ring[3][2048];                      // 24 KB
    __shared__ float bufA[1024], bufB[1024], bufC[1024], bufD[2][1024];// 20 KB
    __shared__ __align__(8) unsigned long long mbar[3];
    const int k = threadIdx.x;      // pair index 0..511
    const int w = k >> 5;           // warp 0..15

    const uint32_t mb0 = (uint32_t)__cvta_generic_to_shared(&mbar[0]);
    const uint32_t rg0 = (uint32_t)__cvta_generic_to_shared(&ring[0][0]);

    if (k == 0) {
        mbar_init(mb0,      1);
        mbar_init(mb0 + 8,  1);
        mbar_init(mb0 + 16, 1);
    }

    // ---- twiddles: one pair per thread, steering pre-permuted -------------
    const float4* tw4 = reinterpret_cast<const float4*>(tw);
    float4 T[10];
#pragma unroll
    for (int j = 0; j < 10; ++j) {
        float4 t = tw4[j * 512 + k];
        const bool rsw = (j <= 8) && (((k >> j) & 1) != 0);        // keep/send rows
        const bool csw = (j >= 1) && (((k >> (j - 1)) & 1) != 0);  // input orientation
        if (rsw) t = make_float4(t.z, t.w, t.x, t.y);
        if (csw) t = make_float4(t.y, t.x, t.w, t.z);
        T[j] = t;
    }
    const float bias0 = bias[k];
    const float bias1 = bias[k + 512];

    const int npairs = (nrows + 1) >> 1;
    __syncthreads();                 // mbarriers initialized

    // ---- prologue: issue bulk loads for iterations 0 and 1 ----------------
    const int pi0 = blockIdx.x;
    if (k == 0) {
#pragma unroll
        for (int d = 0; d < 2; ++d) {
            const int p = pi0 + d * GRID;
            if (p < npairs) {
                const int r0 = 2 * p;
                const uint32_t bytes = (r0 + 1 < nrows) ? 8192u : 4096u;
                mbar_expect_tx(mb0 + 8u * d, bytes);
                bulk_ld(rg0 + 8192u * d, x + (size_t)r0 * 1024, bytes, mb0 + 8u * d);
            }
        }
    }

    int pi = pi0;
    int slot = 0, par = 0;
    while (pi < npairs) {
        // ---- issue bulk load for iteration i+2 (ring slot consumed i-1) ---
        if (k == 0) {
            const int p = pi + 2 * GRID;
            if (p < npairs) {
                int s2 = slot + 2; if (s2 >= 3) s2 -= 3;
                const int r0 = 2 * p;
                const uint32_t bytes = (r0 + 1 < nrows) ? 8192u : 4096u;
                mbar_expect_tx(mb0 + 8u * s2, bytes);
                bulk_ld(rg0 + 8192u * s2, x + (size_t)r0 * 1024, bytes, mb0 + 8u * s2);
            }
        }

        // ---- wait for this iteration's data, read own operands ------------
        mbar_wait(mb0 + 8u * slot, par);
        const float2 A0 = *reinterpret_cast<const float2*>(&ring[slot][2 * k]);
        const float2 A1 = *reinterpret_cast<const float2*>(&ring[slot][1024 + 2 * k]);

        float P0 = A0.x, Q0 = A0.y;   // row 0
        float P1 = A1.x, Q1 = A1.y;   // row 1

#pragma unroll
        for (int j = 0; j < 9; ++j) {
            // keep -> P, send -> S (orientation folded into twiddles)
            float S0 = fmaf(T[j].z, P0, T[j].w * Q0);
            P0       = fmaf(T[j].x, P0, T[j].y * Q0);
            float S1 = fmaf(T[j].z, P1, T[j].w * Q1);
            P1       = fmaf(T[j].x, P1, T[j].y * Q1);

            if (j <= 4) {
                const int d = 1 << j;
                Q0 = __shfl_xor_sync(0xffffffffu, S0, d);
                Q1 = __shfl_xor_sync(0xffffffffu, S1, d);
            } else if (j == 5) {
                bufA[k] = S0; bufA[512 + k] = S1;
                barx(1 + (w >> 1), 64);            // warp-pair {w, w^1}
                Q0 = bufA[k ^ 32]; Q1 = bufA[512 + (k ^ 32)];
            } else if (j == 6) {
                bufB[k] = S0; bufB[512 + k] = S1;
                barx(9 + (w >> 2), 128);           // quad {w & ~3}
                Q0 = bufB[k ^ 64]; Q1 = bufB[512 + (k ^ 64)];
            } else if (j == 7) {
                bufC[k] = S0; bufC[512 + k] = S1;
                barx(13 + (w >> 3), 256);          // octet {w & ~7}
                Q0 = bufC[k ^ 128]; Q1 = bufC[512 + (k ^ 128)];
            } else {  // j == 8
                float* D = bufD[slot & 1];
                D[k] = S0; D[512 + k] = S1;
                barx(15, 512);                     // full block
                Q0 = D[k ^ 256]; Q1 = D[512 + (k ^ 256)];
            }
        }

        // stage 9 (s=512, no exchange) + bias folded into the FMA chain
        const float z0_0 = fmaf(T[9].x, P0, fmaf(T[9].y, Q0, bias0));
        const float z1_0 = fmaf(T[9].z, P0, fmaf(T[9].w, Q0, bias1));
        const float z0_1 = fmaf(T[9].x, P1, fmaf(T[9].y, Q1, bias0));
        const float z1_1 = fmaf(T[9].z, P1, fmaf(T[9].w, Q1, bias1));

        const int r0 = 2 * pi, r1 = 2 * pi + 1;
        {
            float* o = out + (size_t)r0 * 1024;
            __stcs(o + k,       z0_0);
            __stcs(o + k + 512, z1_0);
        }
        if (r1 < nrows) {
            float* o = out + (size_t)r1 * 1024;
            __stcs(o + k,       z0_1);
            __stcs(o + k + 512, z1_1);
        }

        pi += GRID;
        ++slot;
        if (slot == 3) { slot = 0; par ^= 1; }
    }
}

extern "C" void kernel_launch(void* const* d_in, const int* in_sizes, int n_in,
                              void* d_out, int out_size)
{
    const float* x  = nullptr;
    const float* tw = nullptr;
    const float* bs = nullptr;
    long long x_elems = 0;
    for (int i = 0; i < n_in; ++i) {
        if (in_sizes[i] == 20480)     tw = (const float*)d_in[i];
        else if (in_sizes[i] == 1024) bs = (const float*)d_in[i];
        else { x = (const float*)d_in[i]; x_elems = in_sizes[i]; }
    }
    const int nrows = (int)(x_elems / 1024);

    butterfly_kernel<<<GRID, TPB>>>(x, tw, bs, (float*)d_out, nrows);
}

// round 10
// speedup vs baseline: 1.0255x; 1.0255x over previous
#include <cuda_runtime.h>
#include <cstddef>
#include <cstdint>

// Butterfly n=1024, log_n=10, increasing stride, + bias. 32768 rows.
//
// R9 = R8 (512 thr, one pair/thread; exchanges: stages 0-4 shfl_xor, 5-8
// smem w/ minimal-scope named barriers; TMA bulk 3-slot input ring, dist 2;
// __stcs outputs) + DEFERRED SCALING:
// values carried as c*vhat with static per-(thread,stage) scales; each stage
// becomes Phat' = Phat + alpha*Qhat ; Shat = Phat + beta*Qhat  (2 FMA instead
// of 4). alpha/beta precomputed at init from own and partner scale chains
// (kept-path scale = product of own pre-permuted T.x; received scale =
// partner's T.z * partner's chain). Scales folded back in stage 9 with bias.
// Also fixes R8's bufD parity bug (slot&1 repeats across the 2->0 wrap).

constexpr int TPB  = 512;
constexpr int GRID = 296;

__device__ __forceinline__ void barx(int id, int cnt) {
    asm volatile("bar.sync %0, %1;" :: "r"(id), "r"(cnt) : "memory");
}
__device__ __forceinline__ void mbar_init(uint32_t a, uint32_t cnt) {
    asm volatile("mbarrier.init.shared.b64 [%0], %1;" :: "r"(a), "r"(cnt) : "memory");
}
__device__ __forceinline__ void mbar_expect_tx(uint32_t a, uint32_t bytes) {
    asm volatile("mbarrier.arrive.expect_tx.shared.b64 _, [%0], %1;" :: "r"(a), "r"(bytes) : "memory");
}
__device__ __forceinline__ void bulk_ld(uint32_t dst, const void* src, uint32_t bytes, uint32_t mbar) {
    asm volatile("cp.async.bulk.shared::cta.global.mbarrier::complete_tx::bytes [%0], [%1], %2, [%3];"
                 :: "r"(dst), "l"(src), "r"(bytes), "r"(mbar) : "memory");
}
__device__ __forceinline__ void mbar_wait(uint32_t a, uint32_t parity) {
    asm volatile(
        "{\n\t"
        ".reg .pred P;\n\t"
        "LW%=:\n\t"
        "mbarrier.try_wait.parity.acquire.cta.shared::cta.b64 P, [%0], %1, 0x989680;\n\t"
        "@P bra.uni LD%=;\n\t"
        "bra.uni LW%=;\n\t"
        "LD%=:\n\t"
        "}"
        :: "r"(a), "r"(parity) : "memory");
}

// pre-permuted twiddle for (thread p, stage i): same steering as R4/R8
__device__ __forceinline__ float4 loadT(const float4* tw4, int p, int i) {
    float4 t = tw4[i * 512 + p];
    const bool rsw = (i <= 8) && (((p >> i) & 1) != 0);
    const bool csw = (i >= 1) && (((p >> (i - 1)) & 1) != 0);
    if (rsw) t = make_float4(t.z, t.w, t.x, t.y);
    if (csw) t = make_float4(t.y, t.x, t.w, t.z);
    return t;
}

__global__ __launch_bounds__(TPB, 2)
void butterfly_kernel(const float* __restrict__ x,
                      const float* __restrict__ tw,
                      const float* __restrict__ bias,
                      float* __restrict__ out,
                      int nrows)
{
    __shared__ __align__(16) float ring[3][2048];                      // 24 KB
    __shared__ float bufA[1024], bufB[1024], bufC[1024], bufD[2][1024];// 20 KB
    __shared__ __align__(8) unsigned long long mbar[3];
    const int k = threadIdx.x;      // pair index 0..511
    const int w = k >> 5;           // warp 0..15

    const uint32_t mb0 = (uint32_t)__cvta_generic_to_shared(&mbar[0]);
    const uint32_t rg0 = (uint32_t)__cvta_generic_to_shared(&ring[0][0]);

    if (k == 0) {
        mbar_init(mb0,      1);
        mbar_init(mb0 + 8,  1);
        mbar_init(mb0 + 16, 1);
    }

    // ---- deferred-scaling coefficients ------------------------------------
    const float4* tw4 = reinterpret_cast<const float4*>(tw);
    float alp[9], bet[9];
    float cP = 1.f;     // own kept-path scale entering stage j
    float sQ = 1.f;     // scale of the Q input of stage j (stage 0: raw)
#pragma unroll
    for (int j = 0; j < 9; ++j) {
        const float4 tj = loadT(tw4, k, j);
        alp[j] = (tj.y * sQ) / (tj.x * cP);
        bet[j] = (tj.w * sQ) / (tj.z * cP);
        // scale of value received after stage j = partner's sent scale
        const int p = k ^ (1 << j);
        float c = 1.f;
        for (int i = 0; i < j; ++i) c *= loadT(tw4, p, i).x;
        sQ = loadT(tw4, p, j).z * c;
        cP = tj.x * cP;
    }
    const float4 t9 = loadT(tw4, k, 9);
    const float A0 = t9.x * cP, B0 = t9.y * sQ;
    const float A1 = t9.z * cP, B1 = t9.w * sQ;
    const float bias0 = bias[k];
    const float bias1 = bias[k + 512];

    const int npairs = (nrows + 1) >> 1;
    __syncthreads();                 // mbarriers initialized

    // ---- prologue: issue bulk loads for iterations 0 and 1 ----------------
    const int pi0 = blockIdx.x;
    if (k == 0) {
#pragma unroll
        for (int d = 0; d < 2; ++d) {
            const int p = pi0 + d * GRID;
            if (p < npairs) {
                const int r0 = 2 * p;
                const uint32_t bytes = (r0 + 1 < nrows) ? 8192u : 4096u;
                mbar_expect_tx(mb0 + 8u * d, bytes);
                bulk_ld(rg0 + 8192u * d, x + (size_t)r0 * 1024, bytes, mb0 + 8u * d);
            }
        }
    }

    int pi = pi0;
    int slot = 0, par = 0, dpar = 0;
    while (pi < npairs) {
        // ---- issue bulk load for iteration i+2 -----------------------------
        if (k == 0) {
            const int p = pi + 2 * GRID;
            if (p < npairs) {
                int s2 = slot + 2; if (s2 >= 3) s2 -= 3;
                const int r0 = 2 * p;
                const uint32_t bytes = (r0 + 1 < nrows) ? 8192u : 4096u;
                mbar_expect_tx(mb0 + 8u * s2, bytes);
                bulk_ld(rg0 + 8192u * s2, x + (size_t)r0 * 1024, bytes, mb0 + 8u * s2);
            }
        }

        // ---- wait for this iteration's data, read own operands -------------
        mbar_wait(mb0 + 8u * slot, par);
        const float2 Ain0 = *reinterpret_cast<const float2*>(&ring[slot][2 * k]);
        const float2 Ain1 = *reinterpret_cast<const float2*>(&ring[slot][1024 + 2 * k]);

        float P0 = Ain0.x, Q0 = Ain0.y;   // row 0 (hatted values; scale 1 at entry)
        float P1 = Ain1.x, Q1 = Ain1.y;   // row 1

#pragma unroll
        for (int j = 0; j < 9; ++j) {
            // deferred-scaled stage: send = P + beta*Q, keep = P + alpha*Q
            const float S0 = fmaf(bet[j], Q0, P0);
            P0             = fmaf(alp[j], Q0, P0);
            const float S1 = fmaf(bet[j], Q1, P1);
            P1             = fmaf(alp[j], Q1, P1);

            if (j <= 4) {
                const int d = 1 << j;
                Q0 = __shfl_xor_sync(0xffffffffu, S0, d);
                Q1 = __shfl_xor_sync(0xffffffffu, S1, d);
            } else if (j == 5) {
                bufA[k] = S0; bufA[512 + k] = S1;
                barx(1 + (w >> 1), 64);            // warp-pair {w, w^1}
                Q0 = bufA[k ^ 32]; Q1 = bufA[512 + (k ^ 32)];
            } else if (j == 6) {
                bufB[k] = S0; bufB[512 + k] = S1;
                barx(9 + (w >> 2), 128);           // quad {w & ~3}
                Q0 = bufB[k ^ 64]; Q1 = bufB[512 + (k ^ 64)];
            } else if (j == 7) {
                bufC[k] = S0; bufC[512 + k] = S1;
                barx(13 + (w >> 3), 256);          // octet {w & ~7}
                Q0 = bufC[k ^ 128]; Q1 = bufC[512 + (k ^ 128)];
            } else {  // j == 8
                float* D = bufD[dpar];
                D[k] = S0; D[512 + k] = S1;
                barx(15, 512);                     // full block
                Q0 = D[k ^ 256]; Q1 = D[512 + (k ^ 256)];
            }
        }

        // stage 9: fold scales back, add bias
        const float z0_0 = fmaf(A0, P0, fmaf(B0, Q0, bias0));
        const float z1_0 = fmaf(A1, P0, fmaf(B1, Q0, bias1));
        const float z0_1 = fmaf(A0, P1, fmaf(B0, Q1, bias0));
        const float z1_1 = fmaf(A1, P1, fmaf(B1, Q1, bias1));

        const int r0 = 2 * pi, r1 = 2 * pi + 1;
        {
            float* o = out + (size_t)r0 * 1024;
            __stcs(o + k,       z0_0);
            __stcs(o + k + 512, z1_0);
        }
        if (r1 < nrows) {
            float* o = out + (size_t)r1 * 1024;
            __stcs(o + k,       z0_1);
            __stcs(o + k + 512, z1_1);
        }

        pi += GRID;
        dpar ^= 1;
        ++slot;
        if (slot == 3) { slot = 0; par ^= 1; }
    }
}

extern "C" void kernel_launch(void* const* d_in, const int* in_sizes, int n_in,
                              void* d_out, int out_size)
{
    const float* x  = nullptr;
    const float* tw = nullptr;
    const float* bs = nullptr;
    long long x_elems = 0;
    for (int i = 0; i < n_in; ++i) {
        if (in_sizes[i] == 20480)     tw = (const float*)d_in[i];
        else if (in_sizes[i] == 1024) bs = (const float*)d_in[i];
        else { x = (const float*)d_in[i]; x_elems = in_sizes[i]; }
    }
    const int nrows = (int)(x_elems / 1024);

    butterfly_kernel<<<GRID, TPB>>>(x, tw, bs, (float*)d_out, nrows);
}

// round 11
// speedup vs baseline: 1.0443x; 1.0183x over previous
#include <cuda_runtime.h>
#include <cstddef>
#include <cstdint>

// Butterfly n=1024, log_n=10, increasing stride, + bias. 32768 rows.
//
// R9 = R8 (512 thr, one pair/thread; exchanges: stages 0-4 shfl_xor, 5-8
// smem w/ minimal-scope named barriers; TMA bulk 3-slot input ring, dist 2;
// __stcs outputs) + DEFERRED SCALING:
// values carried as c*vhat with static per-(thread,stage) scales; each stage
// becomes Phat' = Phat + alpha*Qhat ; Shat = Phat + beta*Qhat  (2 FMA instead
// of 4). alpha/beta precomputed at init from own and partner scale chains
// (kept-path scale = product of own pre-permuted T.x; received scale =
// partner's T.z * partner's chain). Scales folded back in stage 9 with bias.
// Also fixes R8's bufD parity bug (slot&1 repeats across the 2->0 wrap).

constexpr int TPB  = 512;
constexpr int GRID = 296;

__device__ __forceinline__ void barx(int id, int cnt) {
    asm volatile("bar.sync %0, %1;" :: "r"(id), "r"(cnt) : "memory");
}
__device__ __forceinline__ void mbar_init(uint32_t a, uint32_t cnt) {
    asm volatile("mbarrier.init.shared.b64 [%0], %1;" :: "r"(a), "r"(cnt) : "memory");
}
__device__ __forceinline__ void mbar_expect_tx(uint32_t a, uint32_t bytes) {
    asm volatile("mbarrier.arrive.expect_tx.shared.b64 _, [%0], %1;" :: "r"(a), "r"(bytes) : "memory");
}
__device__ __forceinline__ void bulk_ld(uint32_t dst, const void* src, uint32_t bytes, uint32_t mbar) {
    asm volatile("cp.async.bulk.shared::cta.global.mbarrier::complete_tx::bytes [%0], [%1], %2, [%3];"
                 :: "r"(dst), "l"(src), "r"(bytes), "r"(mbar) : "memory");
}
__device__ __forceinline__ void mbar_wait(uint32_t a, uint32_t parity) {
    asm volatile(
        "{\n\t"
        ".reg .pred P;\n\t"
        "LW%=:\n\t"
        "mbarrier.try_wait.parity.acquire.cta.shared::cta.b64 P, [%0], %1, 0x989680;\n\t"
        "@P bra.uni LD%=;\n\t"
        "bra.uni LW%=;\n\t"
        "LD%=:\n\t"
        "}"
        :: "r"(a), "r"(parity) : "memory");
}

// pre-permuted twiddle for (thread p, stage i): same steering as R4/R8
__device__ __forceinline__ float4 loadT(const float4* tw4, int p, int i) {
    float4 t = tw4[i * 512 + p];
    const bool rsw = (i <= 8) && (((p >> i) & 1) != 0);
    const bool csw = (i >= 1) && (((p >> (i - 1)) & 1) != 0);
    if (rsw) t = make_float4(t.z, t.w, t.x, t.y);
    if (csw) t = make_float4(t.y, t.x, t.w, t.z);
    return t;
}

__global__ __launch_bounds__(TPB, 2)
void butterfly_kernel(const float* __restrict__ x,
                      const float* __restrict__ tw,
                      const float* __restrict__ bias,
                      float* __restrict__ out,
                      int nrows)
{
    __shared__ __align__(16) float ring[3][2048];                      // 24 KB
    __shared__ float bufA[1024], bufB[1024], bufC[1024], bufD[2][1024];// 20 KB
    __shared__ __align__(8) unsigned long long mbar[3];
    const int k = threadIdx.x;      // pair index 0..511
    const int w = k >> 5;           // warp 0..15

    const uint32_t mb0 = (uint32_t)__cvta_generic_to_shared(&mbar[0]);
    const uint32_t rg0 = (uint32_t)__cvta_generic_to_shared(&ring[0][0]);

    if (k == 0) {
        mbar_init(mb0,      1);
        mbar_init(mb0 + 8,  1);
        mbar_init(mb0 + 16, 1);
    }

    // ---- deferred-scaling coefficients ------------------------------------
    const float4* tw4 = reinterpret_cast<const float4*>(tw);
    float alp[9], bet[9];
    float cP = 1.f;     // own kept-path scale entering stage j
    float sQ = 1.f;     // scale of the Q input of stage j (stage 0: raw)
#pragma unroll
    for (int j = 0; j < 9; ++j) {
        const float4 tj = loadT(tw4, k, j);
        alp[j] = (tj.y * sQ) / (tj.x * cP);
        bet[j] = (tj.w * sQ) / (tj.z * cP);
        // scale of value received after stage j = partner's sent scale
        const int p = k ^ (1 << j);
        float c = 1.f;
        for (int i = 0; i < j; ++i) c *= loadT(tw4, p, i).x;
        sQ = loadT(tw4, p, j).z * c;
        cP = tj.x * cP;
    }
    const float4 t9 = loadT(tw4, k, 9);
    const float A0 = t9.x * cP, B0 = t9.y * sQ;
    const float A1 = t9.z * cP, B1 = t9.w * sQ;
    const float bias0 = bias[k];
    const float bias1 = bias[k + 512];

    const int npairs = (nrows + 1) >> 1;
    __syncthreads();                 // mbarriers initialized

    // ---- prologue: issue bulk loads for iterations 0 and 1 ----------------
    const int pi0 = blockIdx.x;
    if (k == 0) {
#pragma unroll
        for (int d = 0; d < 2; ++d) {
            const int p = pi0 + d * GRID;
            if (p < npairs) {
                const int r0 = 2 * p;
                const uint32_t bytes = (r0 + 1 < nrows) ? 8192u : 4096u;
                mbar_expect_tx(mb0 + 8u * d, bytes);
                bulk_ld(rg0 + 8192u * d, x + (size_t)r0 * 1024, bytes, mb0 + 8u * d);
            }
        }
    }

    int pi = pi0;
    int slot = 0, par = 0, dpar = 0;
    while (pi < npairs) {
        // ---- issue bulk load for iteration i+2 -----------------------------
        if (k == 0) {
            const int p = pi + 2 * GRID;
            if (p < npairs) {
                int s2 = slot + 2; if (s2 >= 3) s2 -= 3;
                const int r0 = 2 * p;
                const uint32_t bytes = (r0 + 1 < nrows) ? 8192u : 4096u;
                mbar_expect_tx(mb0 + 8u * s2, bytes);
                bulk_ld(rg0 + 8192u * s2, x + (size_t)r0 * 1024, bytes, mb0 + 8u * s2);
            }
        }

        // ---- wait for this iteration's data, read own operands -------------
        mbar_wait(mb0 + 8u * slot, par);
        const float2 Ain0 = *reinterpret_cast<const float2*>(&ring[slot][2 * k]);
        const float2 Ain1 = *reinterpret_cast<const float2*>(&ring[slot][1024 + 2 * k]);

        float P0 = Ain0.x, Q0 = Ain0.y;   // row 0 (hatted values; scale 1 at entry)
        float P1 = Ain1.x, Q1 = Ain1.y;   // row 1

#pragma unroll
        for (int j = 0; j < 9; ++j) {
            // deferred-scaled stage: send = P + beta*Q, keep = P + alpha*Q
            const float S0 = fmaf(bet[j], Q0, P0);
            P0             = fmaf(alp[j], Q0, P0);
            const float S1 = fmaf(bet[j], Q1, P1);
            P1             = fmaf(alp[j], Q1, P1);

            if (j <= 4) {
                const int d = 1 << j;
                Q0 = __shfl_xor_sync(0xffffffffu, S0, d);
                Q1 = __shfl_xor_sync(0xffffffffu, S1, d);
            } else if (j == 5) {
                bufA[k] = S0; bufA[512 + k] = S1;
                barx(1 + (w >> 1), 64);            // warp-pair {w, w^1}
                Q0 = bufA[k ^ 32]; Q1 = bufA[512 + (k ^ 32)];
            } else if (j == 6) {
                bufB[k] = S0; bufB[512 + k] = S1;
                barx(9 + (w >> 2), 128);           // quad {w & ~3}
                Q0 = bufB[k ^ 64]; Q1 = bufB[512 + (k ^ 64)];
            } else if (j == 7) {
                bufC[k] = S0; bufC[512 + k] = S1;
                barx(13 + (w >> 3), 256);          // octet {w & ~7}
                Q0 = bufC[k ^ 128]; Q1 = bufC[512 + (k ^ 128)];
            } else {  // j == 8
                float* D = bufD[dpar];
                D[k] = S0; D[512 + k] = S1;
                barx(15, 512);                     // full block
                Q0 = D[k ^ 256]; Q1 = D[512 + (k ^ 256)];
            }
        }

        // stage 9: fold scales back, add bias
        const float z0_0 = fmaf(A0, P0, fmaf(B0, Q0, bias0));
        const float z1_0 = fmaf(A1, P0, fmaf(B1, Q0, bias1));
        const float z0_1 = fmaf(A0, P1, fmaf(B0, Q1, bias0));
        const float z1_1 = fmaf(A1, P1, fmaf(B1, Q1, bias1));

        const int r0 = 2 * pi, r1 = 2 * pi + 1;
        {
            float* o = out + (size_t)r0 * 1024;
            __stcs(o + k,       z0_0);
            __stcs(o + k + 512, z1_0);
        }
        if (r1 < nrows) {
            float* o = out + (size_t)r1 * 1024;
            __stcs(o + k,       z0_1);
            __stcs(o + k + 512, z1_1);
        }

        pi += GRID;
        dpar ^= 1;
        ++slot;
        if (slot == 3) { slot = 0; par ^= 1; }
    }
}

extern "C" void kernel_launch(void* const* d_in, const int* in_sizes, int n_in,
                              void* d_out, int out_size)
{
    const float* x  = nullptr;
    const float* tw = nullptr;
    const float* bs = nullptr;
    long long x_elems = 0;
    for (int i = 0; i < n_in; ++i) {
        if (in_sizes[i] == 20480)     tw = (const float*)d_in[i];
        else if (in_sizes[i] == 1024) bs = (const float*)d_in[i];
        else { x = (const float*)d_in[i]; x_elems = in_sizes[i]; }
    }
    const int nrows = (int)(x_elems / 1024);

    butterfly_kernel<<<GRID, TPB>>>(x, tw, bs, (float*)d_out, nrows);
}

// round 12
// speedup vs baseline: 1.0845x; 1.0385x over previous
#include <cuda_runtime.h>
#include <cstddef>
#include <cstdint>

// Butterfly n=1024, log_n=10, increasing stride, + bias. 32768 rows.
//
// R11 = R9 (512 thr, one pair/thread; deferred scaling: 2 FMA/stage/row;
// exchanges: stages 0-4 shfl_xor, 5-8 smem (1 value/exchange) w/ minimal-
// scope named barriers; TMA bulk input ring dist 2; __stcs outputs)
// but with THREE rows per iteration:
//   - barriers per row 4/2 -> 4/3, iterations 55 -> 37
//   - 3 independent chains inside every lockstep region
// Ring slots hold 3 rows (12KB); exchange buffers 3 rows.

constexpr int TPB  = 512;
constexpr int GRID = 296;

__device__ __forceinline__ void barx(int id, int cnt) {
    asm volatile("bar.sync %0, %1;" :: "r"(id), "r"(cnt) : "memory");
}
__device__ __forceinline__ void mbar_init(uint32_t a, uint32_t cnt) {
    asm volatile("mbarrier.init.shared.b64 [%0], %1;" :: "r"(a), "r"(cnt) : "memory");
}
__device__ __forceinline__ void mbar_expect_tx(uint32_t a, uint32_t bytes) {
    asm volatile("mbarrier.arrive.expect_tx.shared.b64 _, [%0], %1;" :: "r"(a), "r"(bytes) : "memory");
}
__device__ __forceinline__ void bulk_ld(uint32_t dst, const void* src, uint32_t bytes, uint32_t mbar) {
    asm volatile("cp.async.bulk.shared::cta.global.mbarrier::complete_tx::bytes [%0], [%1], %2, [%3];"
                 :: "r"(dst), "l"(src), "r"(bytes), "r"(mbar) : "memory");
}
__device__ __forceinline__ void mbar_wait(uint32_t a, uint32_t parity) {
    asm volatile(
        "{\n\t"
        ".reg .pred P;\n\t"
        "LW%=:\n\t"
        "mbarrier.try_wait.parity.acquire.cta.shared::cta.b64 P, [%0], %1, 0x989680;\n\t"
        "@P bra.uni LD%=;\n\t"
        "bra.uni LW%=;\n\t"
        "LD%=:\n\t"
        "}"
        :: "r"(a), "r"(parity) : "memory");
}

// pre-permuted twiddle for (thread p, stage i)
__device__ __forceinline__ float4 loadT(const float4* tw4, int p, int i) {
    float4 t = tw4[i * 512 + p];
    const bool rsw = (i <= 8) && (((p >> i) & 1) != 0);
    const bool csw = (i >= 1) && (((p >> (i - 1)) & 1) != 0);
    if (rsw) t = make_float4(t.z, t.w, t.x, t.y);
    if (csw) t = make_float4(t.y, t.x, t.w, t.z);
    return t;
}

__global__ __launch_bounds__(TPB, 2)
void butterfly_kernel(const float* __restrict__ x,
                      const float* __restrict__ tw,
                      const float* __restrict__ bias,
                      float* __restrict__ out,
                      int nrows)
{
    __shared__ __align__(16) float ring[3][3072];                       // 36 KB
    __shared__ float bufA[1536], bufB[1536], bufC[1536], bufD[2][1536]; // 30 KB
    __shared__ __align__(8) unsigned long long mbar[3];
    const int k = threadIdx.x;      // pair index 0..511
    const int w = k >> 5;           // warp 0..15

    const uint32_t mb0 = (uint32_t)__cvta_generic_to_shared(&mbar[0]);
    const uint32_t rg0 = (uint32_t)__cvta_generic_to_shared(&ring[0][0]);

    if (k == 0) {
        mbar_init(mb0,      1);
        mbar_init(mb0 + 8,  1);
        mbar_init(mb0 + 16, 1);
    }

    // ---- deferred-scaling coefficients ------------------------------------
    const float4* tw4 = reinterpret_cast<const float4*>(tw);
    float alp[9], bet[9];
    float cP = 1.f;     // own kept-path scale entering stage j
    float sQ = 1.f;     // scale of the Q input of stage j
#pragma unroll
    for (int j = 0; j < 9; ++j) {
        const float4 tj = loadT(tw4, k, j);
        alp[j] = (tj.y * sQ) / (tj.x * cP);
        bet[j] = (tj.w * sQ) / (tj.z * cP);
        const int p = k ^ (1 << j);
        float c = 1.f;
        for (int i = 0; i < j; ++i) c *= loadT(tw4, p, i).x;
        sQ = loadT(tw4, p, j).z * c;
        cP = tj.x * cP;
    }
    const float4 t9 = loadT(tw4, k, 9);
    const float FA0 = t9.x * cP, FB0 = t9.y * sQ;
    const float FA1 = t9.z * cP, FB1 = t9.w * sQ;
    const float bias0 = bias[k];
    const float bias1 = bias[k + 512];

    const int ntrip = (nrows + 2) / 3;
    __syncthreads();                 // mbarriers initialized

    // ---- prologue: issue bulk loads for iterations 0 and 1 ----------------
    const int pi0 = blockIdx.x;
    if (k == 0) {
#pragma unroll
        for (int d = 0; d < 2; ++d) {
            const int p = pi0 + d * GRID;
            if (p < ntrip) {
                const int r0 = 3 * p;
                const int nv = (nrows - r0 >= 3) ? 3 : (nrows - r0);
                mbar_expect_tx(mb0 + 8u * d, (uint32_t)nv * 4096u);
                bulk_ld(rg0 + 12288u * d, x + (size_t)r0 * 1024,
                        (uint32_t)nv * 4096u, mb0 + 8u * d);
            }
        }
    }

    int pi = pi0;
    int slot = 0, par = 0, dpar = 0;
    while (pi < ntrip) {
        // ---- issue bulk load for iteration i+2 -----------------------------
        if (k == 0) {
            const int p = pi + 2 * GRID;
            if (p < ntrip) {
                int s2 = slot + 2; if (s2 >= 3) s2 -= 3;
                const int r0 = 3 * p;
                const int nv = (nrows - r0 >= 3) ? 3 : (nrows - r0);
                mbar_expect_tx(mb0 + 8u * s2, (uint32_t)nv * 4096u);
                bulk_ld(rg0 + 12288u * s2, x + (size_t)r0 * 1024,
                        (uint32_t)nv * 4096u, mb0 + 8u * s2);
            }
        }

        // ---- wait for this iteration's data, read own operands -------------
        mbar_wait(mb0 + 8u * slot, par);
        const float2 I0 = *reinterpret_cast<const float2*>(&ring[slot][2 * k]);
        const float2 I1 = *reinterpret_cast<const float2*>(&ring[slot][1024 + 2 * k]);
        const float2 I2 = *reinterpret_cast<const float2*>(&ring[slot][2048 + 2 * k]);

        float P0 = I0.x, Q0 = I0.y;   // row 0
        float P1 = I1.x, Q1 = I1.y;   // row 1
        float P2 = I2.x, Q2 = I2.y;   // row 2

#pragma unroll
        for (int j = 0; j < 9; ++j) {
            const float S0 = fmaf(bet[j], Q0, P0);
            P0             = fmaf(alp[j], Q0, P0);
            const float S1 = fmaf(bet[j], Q1, P1);
            P1             = fmaf(alp[j], Q1, P1);
            const float S2 = fmaf(bet[j], Q2, P2);
            P2             = fmaf(alp[j], Q2, P2);

            if (j <= 4) {
                const int d = 1 << j;
                Q0 = __shfl_xor_sync(0xffffffffu, S0, d);
                Q1 = __shfl_xor_sync(0xffffffffu, S1, d);
                Q2 = __shfl_xor_sync(0xffffffffu, S2, d);
            } else if (j == 5) {
                bufA[k] = S0; bufA[512 + k] = S1; bufA[1024 + k] = S2;
                barx(1 + (w >> 1), 64);            // warp-pair {w, w^1}
                Q0 = bufA[k ^ 32]; Q1 = bufA[512 + (k ^ 32)]; Q2 = bufA[1024 + (k ^ 32)];
            } else if (j == 6) {
                bufB[k] = S0; bufB[512 + k] = S1; bufB[1024 + k] = S2;
                barx(9 + (w >> 2), 128);           // quad {w & ~3}
                Q0 = bufB[k ^ 64]; Q1 = bufB[512 + (k ^ 64)]; Q2 = bufB[1024 + (k ^ 64)];
            } else if (j == 7) {
                bufC[k] = S0; bufC[512 + k] = S1; bufC[1024 + k] = S2;
                barx(13 + (w >> 3), 256);          // octet {w & ~7}
                Q0 = bufC[k ^ 128]; Q1 = bufC[512 + (k ^ 128)]; Q2 = bufC[1024 + (k ^ 128)];
            } else {  // j == 8
                float* D = bufD[dpar];
                D[k] = S0; D[512 + k] = S1; D[1024 + k] = S2;
                barx(15, 512);                     // full block
                Q0 = D[k ^ 256]; Q1 = D[512 + (k ^ 256)]; Q2 = D[1024 + (k ^ 256)];
            }
        }

        // stage 9: fold scales back, add bias
        const float z0_0 = fmaf(FA0, P0, fmaf(FB0, Q0, bias0));
        const float z1_0 = fmaf(FA1, P0, fmaf(FB1, Q0, bias1));
        const float z0_1 = fmaf(FA0, P1, fmaf(FB0, Q1, bias0));
        const float z1_1 = fmaf(FA1, P1, fmaf(FB1, Q1, bias1));
        const float z0_2 = fmaf(FA0, P2, fmaf(FB0, Q2, bias0));
        const float z1_2 = fmaf(FA1, P2, fmaf(FB1, Q2, bias1));

        const int r0 = 3 * pi;
        {
            float* o = out + (size_t)r0 * 1024;
            __stcs(o + k,       z0_0);
            __stcs(o + k + 512, z1_0);
        }
        if (r0 + 1 < nrows) {
            float* o = out + (size_t)(r0 + 1) * 1024;
            __stcs(o + k,       z0_1);
            __stcs(o + k + 512, z1_1);
        }
        if (r0 + 2 < nrows) {
            float* o = out + (size_t)(r0 + 2) * 1024;
            __stcs(o + k,       z0_2);
            __stcs(o + k + 512, z1_2);
        }

        pi += GRID;
        dpar ^= 1;
        ++slot;
        if (slot == 3) { slot = 0; par ^= 1; }
    }
}

extern "C" void kernel_launch(void* const* d_in, const int* in_sizes, int n_in,
                              void* d_out, int out_size)
{
    const float* x  = nullptr;
    const float* tw = nullptr;
    const float* bs = nullptr;
    long long x_elems = 0;
    for (int i = 0; i < n_in; ++i) {
        if (in_sizes[i] == 20480)     tw = (const float*)d_in[i];
        else if (in_sizes[i] == 1024) bs = (const float*)d_in[i];
        else { x = (const float*)d_in[i]; x_elems = in_sizes[i]; }
    }
    const int nrows = (int)(x_elems / 1024);

    butterfly_kernel<<<GRID, TPB>>>(x, tw, bs, (float*)d_out, nrows);
}